// round 6
// baseline (speedup 1.0000x reference)
#include <cuda_runtime.h>
#include <cuda_bf16.h>
#include <cstdint>

// ESN: h_t = tanh(x_t @ W_in^T + h_{t-1} @ W_res^T); out = h_{T-1} [B,H] fp32.
// B=64, T=512, I=128, H=2048.
//
// Round 6: persistent kernel, fine-grained flag sync (no full-grid barriers),
// 32j x 32b warp tiles (LDS 40->32 KB per kc), W resident in smem, h ping-pong.
// fp32 emulated as 3 bf16 mma.sync terms (Ah*Bh + Ah*Bl + Al*Bh).

#define BB   64
#define TT   512
#define II   128
#define HH   2048
#define NJG  16
#define NKS  9
#define KC1  256
#define NTHR 256
#define NCTA (NJG * NKS)          // 144
#define ASTRIDE 528               // bytes per j-row (512 data + 16 pad)
#define TSZA (128 * ASTRIDE)      // 67584 per A term
#define BSTRIDE 528
#define TSZB (BB * BSTRIDE)       // 33792 per B term
#define BOFF (2 * TSZA)
#define SLOT (2 * TSZA)
#define DYN_SMEM (2 * TSZA + 2 * TSZB)   // 202752

// ---------------- device globals ----------------
__device__ __align__(16) unsigned char  g_wt[NCTA * SLOT];
__device__ __align__(16) __nv_bfloat16  g_xh[BB * TT * II];
__device__ __align__(16) __nv_bfloat16  g_xl[BB * TT * II];
__device__ __align__(16) __nv_bfloat16  g_hh[2][BB * HH];
__device__ __align__(16) __nv_bfloat16  g_hl[2][BB * HH];
__device__ float    g_part[NKS * NJG * 128 * BB];
__device__ volatile unsigned g_pcnt[NJG];   // partials stored, per jg (9/step)
__device__ volatile unsigned g_hcnt[8];     // h slice written, per slice (16/step)
__device__ volatile unsigned g_scnt[8];     // h slice consumed, per slice (16/step)

// ---------------- asm helpers ----------------
__device__ __forceinline__ void mma_bf16(float* d, const uint32_t* a,
                                         uint32_t b0, uint32_t b1) {
    asm volatile(
        "mma.sync.aligned.m16n8k16.row.col.f32.bf16.bf16.f32 "
        "{%0,%1,%2,%3}, {%4,%5,%6,%7}, {%8,%9}, {%0,%1,%2,%3};"
        : "+f"(d[0]), "+f"(d[1]), "+f"(d[2]), "+f"(d[3])
        : "r"(a[0]), "r"(a[1]), "r"(a[2]), "r"(a[3]), "r"(b0), "r"(b1));
}
__device__ __forceinline__ void ldmx4(uint32_t* r, uint32_t addr) {
    asm volatile("ldmatrix.sync.aligned.m8n8.x4.shared.b16 {%0,%1,%2,%3}, [%4];"
        : "=r"(r[0]), "=r"(r[1]), "=r"(r[2]), "=r"(r[3]) : "r"(addr));
}
__device__ __forceinline__ uint32_t smem_u32(const void* p) {
    uint32_t a;
    asm("{ .reg .u64 t; cvta.to.shared.u64 t, %1; cvt.u32.u64 %0, t; }"
        : "=r"(a) : "l"(p));
    return a;
}
__device__ __forceinline__ void spin_ge(volatile unsigned* c, unsigned tgt) {
    while (*c < tgt) { __nanosleep(32); }
}

// ---------------- prep ----------------
__global__ void esn_prep_w(const float* __restrict__ Win, const float* __restrict__ Wres) {
    const int total = HH * (II + HH);
    for (int idx = blockIdx.x * blockDim.x + threadIdx.x; idx < total;
         idx += gridDim.x * blockDim.x) {
        int j = idx / (II + HH);
        int k = idx % (II + HH);
        int jg = j >> 7, jl = j & 127;
        int ks, kl;
        float w;
        if (k < II) { ks = 0; kl = k; w = Win[j * II + k]; }
        else { int kk = k - II; ks = 1 + (kk >> 8); kl = kk & 255; w = Wres[j * HH + kk]; }
        __nv_bfloat16 hi = __float2bfloat16(w);
        float r = w - __bfloat162float(hi);
        __nv_bfloat16 lo = __float2bfloat16(r);
        unsigned base = (unsigned)(jg * NKS + ks) * SLOT + (unsigned)jl * ASTRIDE + (unsigned)kl * 2;
        *(__nv_bfloat16*)(g_wt + base)        = hi;
        *(__nv_bfloat16*)(g_wt + base + TSZA) = lo;
    }
}

__global__ void esn_prep_x(const float* __restrict__ x) {
    const int total = BB * TT * II;
    for (int idx = blockIdx.x * blockDim.x + threadIdx.x; idx < total;
         idx += gridDim.x * blockDim.x) {
        float v = x[idx];
        __nv_bfloat16 hi = __float2bfloat16(v);
        float r = v - __bfloat162float(hi);
        g_xh[idx] = hi;
        g_xl[idx] = __float2bfloat16(r);
    }
}

__global__ void esn_cnt0() {
    int i = threadIdx.x;
    if (i < NJG) *(unsigned*)&g_pcnt[i] = 0u;
    if (i < 8)  { *(unsigned*)&g_hcnt[i] = 0u; *(unsigned*)&g_scnt[i] = 0u; }
}

// ---------------- persistent kernel ----------------
__global__ __launch_bounds__(NTHR, 1) void esn_run(float* __restrict__ out) {
    extern __shared__ __align__(16) unsigned char sm[];
    __shared__ float sT[16 * 65];

    const int tid  = threadIdx.x;
    const int wid  = tid >> 5;
    const int l    = tid & 31;
    const int wj   = wid >> 1;            // 0..3: j sub-tile (32 rows)
    const int wb   = wid & 1;             // 0..1: b sub-tile (32 cols)
    const int bid  = blockIdx.x;
    const int jg   = bid / NKS;
    const int ks   = bid % NKS;
    const int KC   = ks ? KC1 : II;
    const int kch  = KC >> 4;
    const int cpb  = KC >> 3;
    const int chunks = BB * cpb;

    const uint32_t smA = smem_u32(sm);
    const uint32_t smB = smA + BOFF;

    // ldmatrix lane bases
    const uint32_t aA = smA + (uint32_t)(wj * 32 + ((l >> 3) & 1) * 8 + (l & 7)) * ASTRIDE
                            + (uint32_t)(l >> 4) * 16;
    const uint32_t aB = smB + (uint32_t)(wb * 32 + ((l >> 4) & 1) * 8 + (l & 7)) * BSTRIDE
                            + (uint32_t)((l >> 3) & 1) * 16;

    // ---- load W slot into smem once ----
    {
        const uint4* src = (const uint4*)(g_wt + (unsigned)(jg * NKS + ks) * SLOT);
        uint4* dst = (uint4*)sm;
        for (int i = tid; i < SLOT / 16; i += NTHR) dst[i] = src[i];
    }

    // reduce-role constants (bid 0..127)
    const int r_jg = bid >> 3;
    const int r_8  = bid & 7;
    const int r_s  = r_jg >> 1;
    const int jt   = tid >> 4;
    const int b4   = (tid & 15) * 4;

    // ---- stage v_0: ks==0 from x[0], else zeros (h_{-1} = 0) ----
    if (ks == 0) {
        for (int i = tid; i < chunks; i += NTHR) {
            int b = i / cpb, c = i - b * cpb;
            int e = (b * TT + 0) * II + c * 8;
            uint32_t d = (uint32_t)(BOFF + b * BSTRIDE + c * 16);
            *(uint4*)(sm + d)        = *(const uint4*)(g_xh + e);
            *(uint4*)(sm + d + TSZB) = *(const uint4*)(g_xl + e);
        }
    } else {
        const uint4 z = make_uint4(0u, 0u, 0u, 0u);
        for (int i = tid; i < chunks; i += NTHR) {
            int b = i / cpb, c = i - b * cpb;
            uint32_t d = (uint32_t)(BOFF + b * BSTRIDE + c * 16);
            *(uint4*)(sm + d)        = z;
            *(uint4*)(sm + d + TSZB) = z;
        }
    }
    __syncthreads();

    for (int t = 0; t < TT; t++) {
        // ---- MMA: warp = 32j x 32b; 3 terms ----
        float acc[2][4][4];
#pragma unroll
        for (int mi = 0; mi < 2; mi++)
#pragma unroll
            for (int nf = 0; nf < 4; nf++)
#pragma unroll
                for (int i = 0; i < 4; i++) acc[mi][nf][i] = 0.0f;

#pragma unroll 4
        for (int kc = 0; kc < kch; kc++) {
            const uint32_t ka = (uint32_t)kc * 32;
            uint32_t Ah[2][4], Al[2][4], Bh[2][4], Bl[2][4];
            ldmx4(Ah[0], aA + ka);
            ldmx4(Ah[1], aA + 16 * ASTRIDE + ka);
            ldmx4(Al[0], aA + TSZA + ka);
            ldmx4(Al[1], aA + TSZA + 16 * ASTRIDE + ka);
            ldmx4(Bh[0], aB + ka);
            ldmx4(Bh[1], aB + 16 * BSTRIDE + ka);
            ldmx4(Bl[0], aB + TSZB + ka);
            ldmx4(Bl[1], aB + TSZB + 16 * BSTRIDE + ka);
#pragma unroll
            for (int mi = 0; mi < 2; mi++)
#pragma unroll
                for (int nf = 0; nf < 4; nf++) {
                    const int ni = nf >> 1, h8 = (nf & 1) * 2;
                    mma_bf16(acc[mi][nf], Ah[mi], Bh[ni][h8], Bh[ni][h8 + 1]);
                    mma_bf16(acc[mi][nf], Ah[mi], Bl[ni][h8], Bl[ni][h8 + 1]);
                    mma_bf16(acc[mi][nf], Al[mi], Bh[ni][h8], Bh[ni][h8 + 1]);
                }
        }

        // ---- partial stores: P[jl*64 + b] ----
        {
            float* P = g_part + (unsigned)(ks * NJG + jg) * (128 * BB);
            const int jr = l >> 2, bc = (l & 3) * 2;
#pragma unroll
            for (int mi = 0; mi < 2; mi++)
#pragma unroll
                for (int nf = 0; nf < 4; nf++) {
                    const int j = wj * 32 + mi * 16 + jr;
                    const int b = wb * 32 + nf * 8 + bc;
                    *(float2*)&P[j * BB + b]       = make_float2(acc[mi][nf][0], acc[mi][nf][1]);
                    *(float2*)&P[(j + 8) * BB + b] = make_float2(acc[mi][nf][2], acc[mi][nf][3]);
                }
        }
        __syncthreads();
        __threadfence();
        if (tid == 0) atomicAdd((unsigned*)&g_pcnt[jg], 1u);

        // ---- reduce role (bid 0..127): 16j x 64b block ----
        if (bid < 128) {
            if (tid == 0) {
                spin_ge(&g_pcnt[r_jg], 9u * (t + 1));
                if (t >= 2) spin_ge(&g_scnt[r_s], 16u * (t - 1));  // h buffer WAR
            }
            __syncthreads();
            __threadfence();

            const unsigned o = (unsigned)((r_8 * 16 + jt) * 64 + b4);
            float4 s = make_float4(0.f, 0.f, 0.f, 0.f);
#pragma unroll
            for (int kr = 0; kr < NKS; kr++) {
                const float4 v = *(const float4*)(g_part + (unsigned)(kr * NJG + r_jg) * (128 * BB) + o);
                s.x += v.x; s.y += v.y; s.z += v.z; s.w += v.w;
            }
            s.x = tanhf(s.x); s.y = tanhf(s.y); s.z = tanhf(s.z); s.w = tanhf(s.w);
            sT[jt * 65 + b4]     = s.x;
            sT[jt * 65 + b4 + 1] = s.y;
            sT[jt * 65 + b4 + 2] = s.z;
            sT[jt * 65 + b4 + 3] = s.w;
            __syncthreads();

            __nv_bfloat16* hh = g_hh[t & 1];
            __nv_bfloat16* hl = g_hl[t & 1];
            const bool last_t = (t == TT - 1);
#pragma unroll
            for (int it = 0; it < 2; it++) {
                const int idx2 = it * 256 + tid;
                const int p  = idx2 & 7;
                const int bb = idx2 >> 3;
                const float f0 = sT[(2 * p) * 65 + bb];
                const float f1 = sT[(2 * p + 1) * 65 + bb];
                const int jglob = r_jg * 128 + r_8 * 16 + 2 * p;
                __nv_bfloat162 h2 = __floats2bfloat162_rn(f0, f1);
                float r0 = f0 - __bfloat162float(__low2bfloat16(h2));
                float r1 = f1 - __bfloat162float(__high2bfloat16(h2));
                __nv_bfloat162 l2 = __floats2bfloat162_rn(r0, r1);
                *(__nv_bfloat162*)(hh + bb * HH + jglob) = h2;
                *(__nv_bfloat162*)(hl + bb * HH + jglob) = l2;
                if (last_t) *(float2*)&out[bb * HH + jglob] = make_float2(f0, f1);
            }
            __syncthreads();
            __threadfence();
            if (tid == 0) atomicAdd((unsigned*)&g_hcnt[r_s], 1u);
        }
        __syncthreads();   // smem v buffer reuse guard for all CTAs

        // ---- stage v_{t+1} ----
        if (t + 1 < TT) {
            if (tid == 0) {
                const unsigned tg = 16u * (t + 1);
                spin_ge(&g_hcnt[jg >> 1], tg);            // my P consumed (WAR)
                if (ks) spin_ge(&g_hcnt[ks - 1], tg);     // h_t slice ready
            }
            __syncthreads();
            __threadfence();

            if (ks == 0) {
                for (int i = tid; i < chunks; i += NTHR) {
                    int b = i / cpb, c = i - b * cpb;
                    int e = (b * TT + (t + 1)) * II + c * 8;
                    uint32_t d = (uint32_t)(BOFF + b * BSTRIDE + c * 16);
                    *(uint4*)(sm + d)        = *(const uint4*)(g_xh + e);
                    *(uint4*)(sm + d + TSZB) = *(const uint4*)(g_xl + e);
                }
            } else {
                const __nv_bfloat16* hh = g_hh[t & 1];
                const __nv_bfloat16* hl = g_hl[t & 1];
                for (int i = tid; i < chunks; i += NTHR) {
                    int b = i / cpb, c = i - b * cpb;
                    int e = b * HH + (ks - 1) * KC1 + c * 8;
                    uint32_t d = (uint32_t)(BOFF + b * BSTRIDE + c * 16);
                    *(uint4*)(sm + d)        = *(const uint4*)(hh + e);
                    *(uint4*)(sm + d + TSZB) = *(const uint4*)(hl + e);
                }
            }
            __syncthreads();
            if (ks && tid == 0) atomicAdd((unsigned*)&g_scnt[ks - 1], 1u);
        }
    }
}

// ---------------- launcher ----------------
extern "C" void kernel_launch(void* const* d_in, const int* in_sizes, int n_in,
                              void* d_out, int out_size)
{
    const float* x    = (const float*)d_in[0];
    const float* Win  = (const float*)d_in[1];
    const float* Wres = (const float*)d_in[2];
    float* out = (float*)d_out;

    cudaFuncSetAttribute(esn_run, cudaFuncAttributeMaxDynamicSharedMemorySize, DYN_SMEM);

    esn_prep_w<<<2048, 256>>>(Win, Wres);
    esn_prep_x<<<2048, 256>>>(x);
    esn_cnt0<<<1, 32>>>();
    esn_run<<<NCTA, NTHR, DYN_SMEM>>>(out);
}

// round 7
// speedup vs baseline: 1.0929x; 1.0929x over previous
#include <cuda_runtime.h>
#include <cuda_bf16.h>
#include <cstdint>

// ESN: h_t = tanh(x_t @ W_in^T + h_{t-1} @ W_res^T); out = h_{T-1} [B,H] fp32.
// B=64, T=512, I=128, H=2048.
//
// Round 7: round-6 structure (persistent, 144 CTAs, flag sync, 32jx32b warp
// tiles, W in smem) with a CHEAP sync layer:
//  - busy-poll ld.acquire.gpu spins (no __nanosleep wake latency)
//  - red.release.gpu flags (no membar.gl / CCTL.IVALL L1 flushes)
//  - all cross-SM data via .cg (L2-coherent) loads/stores.

#define BB   64
#define TT   512
#define II   128
#define HH   2048
#define NJG  16
#define NKS  9
#define KC1  256
#define NTHR 256
#define NCTA (NJG * NKS)          // 144
#define ASTRIDE 528               // bytes per j-row (512 data + 16 pad)
#define TSZA (128 * ASTRIDE)      // 67584 per A term
#define BSTRIDE 528
#define TSZB (BB * BSTRIDE)       // 33792 per B term
#define BOFF (2 * TSZA)
#define SLOT (2 * TSZA)
#define DYN_SMEM (2 * TSZA + 2 * TSZB)   // 202752

// ---------------- device globals ----------------
__device__ __align__(16) unsigned char  g_wt[NCTA * SLOT];
__device__ __align__(16) __nv_bfloat16  g_xh[BB * TT * II];
__device__ __align__(16) __nv_bfloat16  g_xl[BB * TT * II];
__device__ __align__(16) __nv_bfloat16  g_hh[2][BB * HH];
__device__ __align__(16) __nv_bfloat16  g_hl[2][BB * HH];
__device__ float    g_part[NKS * NJG * 128 * BB];
__device__ unsigned g_pcnt[NJG];   // partials stored, per jg (9/step)
__device__ unsigned g_hcnt[8];     // h slice written, per slice (16/step)
__device__ unsigned g_scnt[8];     // h slice consumed, per slice (16/step)

// ---------------- asm helpers ----------------
__device__ __forceinline__ void mma_bf16(float* d, const uint32_t* a,
                                         uint32_t b0, uint32_t b1) {
    asm volatile(
        "mma.sync.aligned.m16n8k16.row.col.f32.bf16.bf16.f32 "
        "{%0,%1,%2,%3}, {%4,%5,%6,%7}, {%8,%9}, {%0,%1,%2,%3};"
        : "+f"(d[0]), "+f"(d[1]), "+f"(d[2]), "+f"(d[3])
        : "r"(a[0]), "r"(a[1]), "r"(a[2]), "r"(a[3]), "r"(b0), "r"(b1));
}
__device__ __forceinline__ void ldmx4(uint32_t* r, uint32_t addr) {
    asm volatile("ldmatrix.sync.aligned.m8n8.x4.shared.b16 {%0,%1,%2,%3}, [%4];"
        : "=r"(r[0]), "=r"(r[1]), "=r"(r[2]), "=r"(r[3]) : "r"(addr));
}
__device__ __forceinline__ uint32_t smem_u32(const void* p) {
    uint32_t a;
    asm("{ .reg .u64 t; cvta.to.shared.u64 t, %1; cvt.u32.u64 %0, t; }"
        : "=r"(a) : "l"(p));
    return a;
}
// release-flag increment: orders ALL my prior (weak/.cg) accesses before flag
__device__ __forceinline__ void flag_add(unsigned* p) {
    asm volatile("red.release.gpu.global.add.u32 [%0], 1;" :: "l"(p) : "memory");
}
// acquire spin: busy poll, one L2 round trip per iteration
__device__ __forceinline__ void spin_ge(unsigned* c, unsigned tgt) {
    unsigned v;
    do {
        asm volatile("ld.acquire.gpu.global.u32 %0, [%1];"
                     : "=r"(v) : "l"(c) : "memory");
    } while (v < tgt);
}

// ---------------- prep ----------------
__global__ void esn_prep_w(const float* __restrict__ Win, const float* __restrict__ Wres) {
    const int total = HH * (II + HH);
    for (int idx = blockIdx.x * blockDim.x + threadIdx.x; idx < total;
         idx += gridDim.x * blockDim.x) {
        int j = idx / (II + HH);
        int k = idx % (II + HH);
        int jg = j >> 7, jl = j & 127;
        int ks, kl;
        float w;
        if (k < II) { ks = 0; kl = k; w = Win[j * II + k]; }
        else { int kk = k - II; ks = 1 + (kk >> 8); kl = kk & 255; w = Wres[j * HH + kk]; }
        __nv_bfloat16 hi = __float2bfloat16(w);
        float r = w - __bfloat162float(hi);
        __nv_bfloat16 lo = __float2bfloat16(r);
        unsigned base = (unsigned)(jg * NKS + ks) * SLOT + (unsigned)jl * ASTRIDE + (unsigned)kl * 2;
        *(__nv_bfloat16*)(g_wt + base)        = hi;
        *(__nv_bfloat16*)(g_wt + base + TSZA) = lo;
    }
}

__global__ void esn_prep_x(const float* __restrict__ x) {
    const int total = BB * TT * II;
    for (int idx = blockIdx.x * blockDim.x + threadIdx.x; idx < total;
         idx += gridDim.x * blockDim.x) {
        float v = x[idx];
        __nv_bfloat16 hi = __float2bfloat16(v);
        float r = v - __bfloat162float(hi);
        g_xh[idx] = hi;
        g_xl[idx] = __float2bfloat16(r);
    }
}

__global__ void esn_cnt0() {
    int i = threadIdx.x;
    if (i < NJG) g_pcnt[i] = 0u;
    if (i < 8)  { g_hcnt[i] = 0u; g_scnt[i] = 0u; }
}

// ---------------- persistent kernel ----------------
__global__ __launch_bounds__(NTHR, 1) void esn_run(float* __restrict__ out) {
    extern __shared__ __align__(16) unsigned char sm[];
    __shared__ float sT[16 * 65];

    const int tid  = threadIdx.x;
    const int wid  = tid >> 5;
    const int l    = tid & 31;
    const int wj   = wid >> 1;            // 0..3: j sub-tile (32 rows)
    const int wb   = wid & 1;             // 0..1: b sub-tile (32 cols)
    const int bid  = blockIdx.x;
    const int jg   = bid / NKS;
    const int ks   = bid % NKS;
    const int KC   = ks ? KC1 : II;
    const int kch  = KC >> 4;
    const int cpb  = KC >> 3;
    const int chunks = BB * cpb;

    const uint32_t smA = smem_u32(sm);
    const uint32_t smB = smA + BOFF;

    // ldmatrix lane bases
    const uint32_t aA = smA + (uint32_t)(wj * 32 + ((l >> 3) & 1) * 8 + (l & 7)) * ASTRIDE
                            + (uint32_t)(l >> 4) * 16;
    const uint32_t aB = smB + (uint32_t)(wb * 32 + ((l >> 4) & 1) * 8 + (l & 7)) * BSTRIDE
                            + (uint32_t)((l >> 3) & 1) * 16;

    // ---- load W slot into smem once ----
    {
        const uint4* src = (const uint4*)(g_wt + (unsigned)(jg * NKS + ks) * SLOT);
        uint4* dst = (uint4*)sm;
        for (int i = tid; i < SLOT / 16; i += NTHR) dst[i] = src[i];
    }

    // reduce-role constants (bid 0..127)
    const int r_jg = bid >> 3;
    const int r_8  = bid & 7;
    const int r_s  = r_jg >> 1;
    const int jt   = tid >> 4;
    const int b4   = (tid & 15) * 4;

    // ---- stage v_0: ks==0 from x[0], else zeros (h_{-1} = 0) ----
    if (ks == 0) {
        for (int i = tid; i < chunks; i += NTHR) {
            int b = i / cpb, c = i - b * cpb;
            int e = (b * TT + 0) * II + c * 8;
            uint32_t d = (uint32_t)(BOFF + b * BSTRIDE + c * 16);
            *(uint4*)(sm + d)        = *(const uint4*)(g_xh + e);
            *(uint4*)(sm + d + TSZB) = *(const uint4*)(g_xl + e);
        }
    } else {
        const uint4 z = make_uint4(0u, 0u, 0u, 0u);
        for (int i = tid; i < chunks; i += NTHR) {
            int b = i / cpb, c = i - b * cpb;
            uint32_t d = (uint32_t)(BOFF + b * BSTRIDE + c * 16);
            *(uint4*)(sm + d)        = z;
            *(uint4*)(sm + d + TSZB) = z;
        }
    }
    __syncthreads();

    for (int t = 0; t < TT; t++) {
        // ---- MMA: warp = 32j x 32b; 3 terms ----
        float acc[2][4][4];
#pragma unroll
        for (int mi = 0; mi < 2; mi++)
#pragma unroll
            for (int nf = 0; nf < 4; nf++)
#pragma unroll
                for (int i = 0; i < 4; i++) acc[mi][nf][i] = 0.0f;

#pragma unroll 4
        for (int kc = 0; kc < kch; kc++) {
            const uint32_t ka = (uint32_t)kc * 32;
            uint32_t Ah[2][4], Al[2][4], Bh[2][4], Bl[2][4];
            ldmx4(Ah[0], aA + ka);
            ldmx4(Ah[1], aA + 16 * ASTRIDE + ka);
            ldmx4(Al[0], aA + TSZA + ka);
            ldmx4(Al[1], aA + TSZA + 16 * ASTRIDE + ka);
            ldmx4(Bh[0], aB + ka);
            ldmx4(Bh[1], aB + 16 * BSTRIDE + ka);
            ldmx4(Bl[0], aB + TSZB + ka);
            ldmx4(Bl[1], aB + TSZB + 16 * BSTRIDE + ka);
#pragma unroll
            for (int mi = 0; mi < 2; mi++)
#pragma unroll
                for (int nf = 0; nf < 4; nf++) {
                    const int ni = nf >> 1, h8 = (nf & 1) * 2;
                    mma_bf16(acc[mi][nf], Ah[mi], Bh[ni][h8], Bh[ni][h8 + 1]);
                    mma_bf16(acc[mi][nf], Ah[mi], Bl[ni][h8], Bl[ni][h8 + 1]);
                    mma_bf16(acc[mi][nf], Al[mi], Bh[ni][h8], Bh[ni][h8 + 1]);
                }
        }

        // ---- partial stores (.cg, L2-coherent): P[jl*64 + b] ----
        {
            float* P = g_part + (unsigned)(ks * NJG + jg) * (128 * BB);
            const int jr = l >> 2, bc = (l & 3) * 2;
#pragma unroll
            for (int mi = 0; mi < 2; mi++)
#pragma unroll
                for (int nf = 0; nf < 4; nf++) {
                    const int j = wj * 32 + mi * 16 + jr;
                    const int b = wb * 32 + nf * 8 + bc;
                    __stcg((float2*)&P[j * BB + b],
                           make_float2(acc[mi][nf][0], acc[mi][nf][1]));
                    __stcg((float2*)&P[(j + 8) * BB + b],
                           make_float2(acc[mi][nf][2], acc[mi][nf][3]));
                }
        }
        __syncthreads();
        if (tid == 0) flag_add(&g_pcnt[jg]);

        // ---- reduce role (bid 0..127): 16j x 64b block ----
        if (bid < 128) {
            if (tid == 0) {
                spin_ge(&g_pcnt[r_jg], 9u * (t + 1));
                if (t >= 2) spin_ge(&g_scnt[r_s], 16u * (t - 1));  // h buffer WAR
            }
            __syncthreads();

            const unsigned o = (unsigned)((r_8 * 16 + jt) * 64 + b4);
            float4 s = make_float4(0.f, 0.f, 0.f, 0.f);
#pragma unroll
            for (int kr = 0; kr < NKS; kr++) {
                const float4 v = __ldcg((const float4*)
                    (g_part + (unsigned)(kr * NJG + r_jg) * (128 * BB) + o));
                s.x += v.x; s.y += v.y; s.z += v.z; s.w += v.w;
            }
            s.x = tanhf(s.x); s.y = tanhf(s.y); s.z = tanhf(s.z); s.w = tanhf(s.w);
            sT[jt * 65 + b4]     = s.x;
            sT[jt * 65 + b4 + 1] = s.y;
            sT[jt * 65 + b4 + 2] = s.z;
            sT[jt * 65 + b4 + 3] = s.w;
            __syncthreads();

            __nv_bfloat16* hh = g_hh[t & 1];
            __nv_bfloat16* hl = g_hl[t & 1];
            const bool last_t = (t == TT - 1);
#pragma unroll
            for (int it = 0; it < 2; it++) {
                const int idx2 = it * 256 + tid;
                const int p  = idx2 & 7;
                const int bb = idx2 >> 3;
                const float f0 = sT[(2 * p) * 65 + bb];
                const float f1 = sT[(2 * p + 1) * 65 + bb];
                const int jglob = r_jg * 128 + r_8 * 16 + 2 * p;
                __nv_bfloat162 h2 = __floats2bfloat162_rn(f0, f1);
                float r0 = f0 - __bfloat162float(__low2bfloat16(h2));
                float r1 = f1 - __bfloat162float(__high2bfloat16(h2));
                __nv_bfloat162 l2 = __floats2bfloat162_rn(r0, r1);
                __stcg((unsigned*)(hh + bb * HH + jglob), *(unsigned*)&h2);
                __stcg((unsigned*)(hl + bb * HH + jglob), *(unsigned*)&l2);
                if (last_t) *(float2*)&out[bb * HH + jglob] = make_float2(f0, f1);
            }
            __syncthreads();
            if (tid == 0) flag_add(&g_hcnt[r_s]);
        }
        __syncthreads();   // smem v buffer reuse guard for all CTAs

        // ---- stage v_{t+1} ----
        if (t + 1 < TT) {
            if (tid == 0) {
                const unsigned tg = 16u * (t + 1);
                spin_ge(&g_hcnt[jg >> 1], tg);            // my P consumed (WAR)
                if (ks) spin_ge(&g_hcnt[ks - 1], tg);     // h_t slice ready
            }
            __syncthreads();

            if (ks == 0) {
                for (int i = tid; i < chunks; i += NTHR) {
                    int b = i / cpb, c = i - b * cpb;
                    int e = (b * TT + (t + 1)) * II + c * 8;
                    uint32_t d = (uint32_t)(BOFF + b * BSTRIDE + c * 16);
                    *(uint4*)(sm + d)        = *(const uint4*)(g_xh + e);
                    *(uint4*)(sm + d + TSZB) = *(const uint4*)(g_xl + e);
                }
            } else {
                const __nv_bfloat16* hh = g_hh[t & 1];
                const __nv_bfloat16* hl = g_hl[t & 1];
                for (int i = tid; i < chunks; i += NTHR) {
                    int b = i / cpb, c = i - b * cpb;
                    int e = b * HH + (ks - 1) * KC1 + c * 8;
                    uint32_t d = (uint32_t)(BOFF + b * BSTRIDE + c * 16);
                    *(uint4*)(sm + d)        = __ldcg((const uint4*)(hh + e));
                    *(uint4*)(sm + d + TSZB) = __ldcg((const uint4*)(hl + e));
                }
            }
            __syncthreads();
            if (ks && tid == 0) flag_add(&g_scnt[ks - 1]);
        }
    }
}

// ---------------- launcher ----------------
extern "C" void kernel_launch(void* const* d_in, const int* in_sizes, int n_in,
                              void* d_out, int out_size)
{
    const float* x    = (const float*)d_in[0];
    const float* Win  = (const float*)d_in[1];
    const float* Wres = (const float*)d_in[2];
    float* out = (float*)d_out;

    cudaFuncSetAttribute(esn_run, cudaFuncAttributeMaxDynamicSharedMemorySize, DYN_SMEM);

    esn_prep_w<<<2048, 256>>>(Win, Wres);
    esn_prep_x<<<2048, 256>>>(x);
    esn_cnt0<<<1, 32>>>();
    esn_run<<<NCTA, NTHR, DYN_SMEM>>>(out);
}

// round 9
// speedup vs baseline: 1.1277x; 1.0319x over previous
#include <cuda_runtime.h>
#include <cuda_bf16.h>
#include <cstdint>

// ESN: h_t = tanh(x_t @ W_in^T + h_{t-1} @ W_res^T); out = h_{T-1} [B,H] fp32.
// B=64, T=512, I=128, H=2048.
//
// Round 9: round-7 numerics (3-term bf16: Ah*Bh + Ah*Bl + Al*Bh, v hi/lo),
// with 512 threads (16 warps, 16j x 32b tiles) for latency hiding, P ping-pong
// (removes one flag class + reducer WAR wait), tid0 spins + syncthreads.

#define BB   64
#define TT   512
#define II   128
#define HH   2048
#define NJG  16
#define NKS  9
#define KC1  256
#define NTHR 512
#define NCTA (NJG * NKS)          // 144
#define ASTRIDE 528               // bytes per j-row (512 data + 16 pad)
#define TSZA (128 * ASTRIDE)      // 67584 per W term
#define BSTRIDE 528
#define TSZB (BB * BSTRIDE)       // 33792 per v term
#define BOFF (2 * TSZA)
#define SLOT (2 * TSZA)
#define DYN_SMEM (2 * TSZA + 2 * TSZB)   // 202752

// ---------------- device globals ----------------
__device__ __align__(16) unsigned char  g_wt[NCTA * SLOT];
__device__ __align__(16) __nv_bfloat16  g_xh[BB * TT * II];
__device__ __align__(16) __nv_bfloat16  g_xl[BB * TT * II];
__device__ __align__(16) __nv_bfloat16  g_hh[2][BB * HH];
__device__ __align__(16) __nv_bfloat16  g_hl[2][BB * HH];
__device__ float    g_part[2][NKS * NJG * 128 * BB];   // ping-pong by t&1
__device__ unsigned g_pcnt[NJG];   // partials stored, per jg (9/step)
__device__ unsigned g_hcnt[8];     // h slice written, per slice (16/step)

// ---------------- asm helpers ----------------
__device__ __forceinline__ void mma_bf16(float* d, const uint32_t* a,
                                         uint32_t b0, uint32_t b1) {
    asm volatile(
        "mma.sync.aligned.m16n8k16.row.col.f32.bf16.bf16.f32 "
        "{%0,%1,%2,%3}, {%4,%5,%6,%7}, {%8,%9}, {%0,%1,%2,%3};"
        : "+f"(d[0]), "+f"(d[1]), "+f"(d[2]), "+f"(d[3])
        : "r"(a[0]), "r"(a[1]), "r"(a[2]), "r"(a[3]), "r"(b0), "r"(b1));
}
__device__ __forceinline__ void ldmx4(uint32_t* r, uint32_t addr) {
    asm volatile("ldmatrix.sync.aligned.m8n8.x4.shared.b16 {%0,%1,%2,%3}, [%4];"
        : "=r"(r[0]), "=r"(r[1]), "=r"(r[2]), "=r"(r[3]) : "r"(addr));
}
__device__ __forceinline__ uint32_t smem_u32(const void* p) {
    uint32_t a;
    asm("{ .reg .u64 t; cvta.to.shared.u64 t, %1; cvt.u32.u64 %0, t; }"
        : "=r"(a) : "l"(p));
    return a;
}
__device__ __forceinline__ void flag_add(unsigned* p) {
    asm volatile("red.release.gpu.global.add.u32 [%0], 1;" :: "l"(p) : "memory");
}
__device__ __forceinline__ void spin_ge(unsigned* c, unsigned tgt) {
    unsigned v;
    do {
        asm volatile("ld.acquire.gpu.global.u32 %0, [%1];"
                     : "=r"(v) : "l"(c) : "memory");
    } while (v < tgt);
}

// ---------------- prep ----------------
__global__ void esn_prep_w(const float* __restrict__ Win, const float* __restrict__ Wres) {
    const int total = HH * (II + HH);
    for (int idx = blockIdx.x * blockDim.x + threadIdx.x; idx < total;
         idx += gridDim.x * blockDim.x) {
        int j = idx / (II + HH);
        int k = idx % (II + HH);
        int jg = j >> 7, jl = j & 127;
        int ks, kl;
        float w;
        if (k < II) { ks = 0; kl = k; w = Win[j * II + k]; }
        else { int kk = k - II; ks = 1 + (kk >> 8); kl = kk & 255; w = Wres[j * HH + kk]; }
        __nv_bfloat16 hi = __float2bfloat16(w);
        float r = w - __bfloat162float(hi);
        __nv_bfloat16 lo = __float2bfloat16(r);
        unsigned base = (unsigned)(jg * NKS + ks) * SLOT + (unsigned)jl * ASTRIDE + (unsigned)kl * 2;
        *(__nv_bfloat16*)(g_wt + base)        = hi;
        *(__nv_bfloat16*)(g_wt + base + TSZA) = lo;
    }
}

__global__ void esn_prep_x(const float* __restrict__ x) {
    const int total = BB * TT * II;
    for (int idx = blockIdx.x * blockDim.x + threadIdx.x; idx < total;
         idx += gridDim.x * blockDim.x) {
        float v = x[idx];
        __nv_bfloat16 hi = __float2bfloat16(v);
        float r = v - __bfloat162float(hi);
        g_xh[idx] = hi;
        g_xl[idx] = __float2bfloat16(r);
    }
}

__global__ void esn_cnt0() {
    int i = threadIdx.x;
    if (i < NJG) g_pcnt[i] = 0u;
    if (i < 8)  g_hcnt[i] = 0u;
}

// ---------------- persistent kernel ----------------
__global__ __launch_bounds__(NTHR, 1) void esn_run(float* __restrict__ out) {
    extern __shared__ __align__(16) unsigned char sm[];
    __shared__ float sT[16 * 65];

    const int tid  = threadIdx.x;
    const int wid  = tid >> 5;
    const int l    = tid & 31;
    const int wj   = wid >> 1;            // 0..7: 16-row j band
    const int wb   = wid & 1;             // 0..1: 32-col b half
    const int bid  = blockIdx.x;
    const int jg   = bid / NKS;
    const int ks   = bid % NKS;
    const int KC   = ks ? KC1 : II;
    const int kch  = KC >> 4;
    const int cpb  = KC >> 3;             // 16B chunks per b-row
    const int chunks = BB * cpb;

    const uint32_t smA = smem_u32(sm);
    const uint32_t smB = smA + BOFF;

    // ldmatrix lane bases
    const uint32_t aA = smA + (uint32_t)(wj * 16 + ((l >> 3) & 1) * 8 + (l & 7)) * ASTRIDE
                            + (uint32_t)(l >> 4) * 16;
    const uint32_t aB = smB + (uint32_t)(wb * 32 + ((l >> 4) & 1) * 8 + (l & 7)) * BSTRIDE
                            + (uint32_t)((l >> 3) & 1) * 16;

    // ---- load W slot (hi + lo) into smem once ----
    {
        const uint4* src = (const uint4*)(g_wt + (unsigned)(jg * NKS + ks) * SLOT);
        uint4* dst = (uint4*)sm;
        for (int i = tid; i < SLOT / 16; i += NTHR) dst[i] = src[i];
    }

    // reduce-role constants (bid 0..127): 16j x 64b tile
    const int r_jg = bid >> 3;
    const int r_8  = bid & 7;
    const int r_s  = r_jg >> 1;
    const int jt   = tid >> 5;             // 0..15
    const int b2   = (tid & 31) * 2;       // 0..62

    // ---- stage v_0: ks==0 from x[0], else zeros (h_{-1} = 0) ----
    if (ks == 0) {
        for (int i = tid; i < chunks; i += NTHR) {
            int b = i / cpb, c = i - b * cpb;
            int e = (b * TT + 0) * II + c * 8;
            uint32_t d = (uint32_t)(BOFF + b * BSTRIDE + c * 16);
            *(uint4*)(sm + d)        = *(const uint4*)(g_xh + e);
            *(uint4*)(sm + d + TSZB) = *(const uint4*)(g_xl + e);
        }
    } else {
        const uint4 z = make_uint4(0u, 0u, 0u, 0u);
        for (int i = tid; i < chunks; i += NTHR) {
            int b = i / cpb, c = i - b * cpb;
            uint32_t d = (uint32_t)(BOFF + b * BSTRIDE + c * 16);
            *(uint4*)(sm + d)        = z;
            *(uint4*)(sm + d + TSZB) = z;
        }
    }
    __syncthreads();

    for (int t = 0; t < TT; t++) {
        // ---- MMA: warp = 16j x 32b; 3 terms ----
        float acc[4][4];
#pragma unroll
        for (int nf = 0; nf < 4; nf++)
#pragma unroll
            for (int i = 0; i < 4; i++) acc[nf][i] = 0.0f;

#pragma unroll 4
        for (int kc = 0; kc < kch; kc++) {
            const uint32_t ka = (uint32_t)kc * 32;
            uint32_t Ah[4], Al[4], Bh[2][4], Bl[2][4];
            ldmx4(Ah, aA + ka);
            ldmx4(Al, aA + TSZA + ka);
            ldmx4(Bh[0], aB + ka);
            ldmx4(Bh[1], aB + 16 * BSTRIDE + ka);
            ldmx4(Bl[0], aB + TSZB + ka);
            ldmx4(Bl[1], aB + TSZB + 16 * BSTRIDE + ka);
#pragma unroll
            for (int nf = 0; nf < 4; nf++) {
                const int ni = nf >> 1, h8 = (nf & 1) * 2;
                mma_bf16(acc[nf], Ah, Bh[ni][h8], Bh[ni][h8 + 1]);
                mma_bf16(acc[nf], Ah, Bl[ni][h8], Bl[ni][h8 + 1]);
                mma_bf16(acc[nf], Al, Bh[ni][h8], Bh[ni][h8 + 1]);
            }
        }

        // ---- partial stores (.cg) into ping-pong buffer: P[jl*64 + b] ----
        {
            float* P = g_part[t & 1] + (unsigned)(ks * NJG + jg) * (128 * BB);
            const int j0 = wj * 16 + (l >> 2);
            const int bc = (l & 3) * 2;
#pragma unroll
            for (int nf = 0; nf < 4; nf++) {
                const int b = wb * 32 + nf * 8 + bc;
                __stcg((float2*)&P[j0 * BB + b],       make_float2(acc[nf][0], acc[nf][1]));
                __stcg((float2*)&P[(j0 + 8) * BB + b], make_float2(acc[nf][2], acc[nf][3]));
            }
        }
        __syncthreads();                        // all P stores + all v reads done
        if (tid == 0) flag_add(&g_pcnt[jg]);

        // ---- reduce role (bid 0..127): 16j x 64b tile ----
        if (bid < 128) {
            if (tid == 0) spin_ge(&g_pcnt[r_jg], 9u * (t + 1));
            __syncthreads();

            const unsigned o = (unsigned)((r_8 * 16 + jt) * 64 + b2);
            float s0 = 0.f, s1 = 0.f;
            const float* Pb = g_part[t & 1];
#pragma unroll
            for (int kr = 0; kr < NKS; kr++) {
                const float2 v = __ldcg((const float2*)
                    (Pb + (unsigned)(kr * NJG + r_jg) * (128 * BB) + o));
                s0 += v.x; s1 += v.y;
            }
            s0 = tanhf(s0); s1 = tanhf(s1);
            sT[jt * 65 + b2]     = s0;
            sT[jt * 65 + b2 + 1] = s1;
            __syncthreads();                    // transpose handoff

            __nv_bfloat16* hh = g_hh[t & 1];
            __nv_bfloat16* hl = g_hl[t & 1];
            const bool last_t = (t == TT - 1);
            {
                const int p  = tid & 7;         // j pair
                const int bb = tid >> 3;        // batch
                const float f0 = sT[(2 * p) * 65 + bb];
                const float f1 = sT[(2 * p + 1) * 65 + bb];
                const int jglob = r_jg * 128 + r_8 * 16 + 2 * p;
                __nv_bfloat162 h2 = __floats2bfloat162_rn(f0, f1);
                float r0 = f0 - __bfloat162float(__low2bfloat16(h2));
                float r1 = f1 - __bfloat162float(__high2bfloat16(h2));
                __nv_bfloat162 l2 = __floats2bfloat162_rn(r0, r1);
                __stcg((unsigned*)(hh + bb * HH + jglob), *(unsigned*)&h2);
                __stcg((unsigned*)(hl + bb * HH + jglob), *(unsigned*)&l2);
                if (last_t) *(float2*)&out[bb * HH + jglob] = make_float2(f0, f1);
            }
            __syncthreads();                    // all h stores done before flag
            if (tid == 0) flag_add(&g_hcnt[r_s]);
        }

        // ---- stage v_{t+1} ----
        if (t + 1 < TT) {
            if (tid == 0) {
                // P WAR: reducers of my jg done with step t-1 (buffer (t+1)&1)
                if (t >= 1) spin_ge(&g_hcnt[jg >> 1], 16u * t);
                // RAW: h_t slice ready
                if (ks) spin_ge(&g_hcnt[ks - 1], 16u * (t + 1));
            }
            __syncthreads();

            if (ks == 0) {
                for (int i = tid; i < chunks; i += NTHR) {
                    int b = i / cpb, c = i - b * cpb;
                    int e = (b * TT + (t + 1)) * II + c * 8;
                    uint32_t d = (uint32_t)(BOFF + b * BSTRIDE + c * 16);
                    *(uint4*)(sm + d)        = *(const uint4*)(g_xh + e);
                    *(uint4*)(sm + d + TSZB) = *(const uint4*)(g_xl + e);
                }
            } else {
                const __nv_bfloat16* hh = g_hh[t & 1];
                const __nv_bfloat16* hl = g_hl[t & 1];
                for (int i = tid; i < chunks; i += NTHR) {
                    int b = i / cpb, c = i - b * cpb;
                    int e = b * HH + (ks - 1) * KC1 + c * 8;
                    uint32_t d = (uint32_t)(BOFF + b * BSTRIDE + c * 16);
                    *(uint4*)(sm + d)        = __ldcg((const uint4*)(hh + e));
                    *(uint4*)(sm + d + TSZB) = __ldcg((const uint4*)(hl + e));
                }
            }
            __syncthreads();                    // v staged before next MMA
        }
    }
}

// ---------------- launcher ----------------
extern "C" void kernel_launch(void* const* d_in, const int* in_sizes, int n_in,
                              void* d_out, int out_size)
{
    const float* x    = (const float*)d_in[0];
    const float* Win  = (const float*)d_in[1];
    const float* Wres = (const float*)d_in[2];
    float* out = (float*)d_out;

    cudaFuncSetAttribute(esn_run, cudaFuncAttributeMaxDynamicSharedMemorySize, DYN_SMEM);

    esn_prep_w<<<2048, 256>>>(Win, Wres);
    esn_prep_x<<<2048, 256>>>(x);
    esn_cnt0<<<1, 32>>>();
    esn_run<<<NCTA, NTHR, DYN_SMEM>>>(out);
}